// round 15
// baseline (speedup 1.0000x reference)
#include <cuda_runtime.h>
#include <math.h>
#include <stdint.h>

// ---------------- problem constants ----------------
#define kNQ 10000
#define kNS 500
#define kQN 4
#define kSN 10
#define kB  32
#define kS  200
#define kD  128
#define kT  199   // S-1

// ---------------- scratch layout (floats) ----------------
__host__ __device__ constexpr size_t O_TA0 = 0;
__host__ __device__ constexpr size_t O_TA1 = O_TA0 + (size_t)kNQ*kD;
__host__ __device__ constexpr size_t O_TA2 = O_TA1 + (size_t)kNS*kD;
__host__ __device__ constexpr size_t O_TB0 = O_TA2 + (size_t)kNQ*kD;   // reused: QTT
__host__ __device__ constexpr size_t O_TB1 = O_TB0 + (size_t)kNQ*kD;
__host__ __device__ constexpr size_t O_A   = O_TB1 + (size_t)kNS*kD;   // spare
__host__ __device__ constexpr size_t O_H   = O_A   + (size_t)kNQ*kD;  // Ht: [b][d][s]
__host__ __device__ constexpr size_t O_AS  = O_H   + (size_t)kB*kS*kD;
__host__ __device__ constexpr size_t O_V   = O_AS  + (size_t)kB*kT;   // qv[128], kv[128], c_q, c_k
__host__ __device__ constexpr size_t O_RG  = O_V   + 258;             // r_gates 2x512
__host__ __device__ constexpr size_t G_TOTAL = O_RG + 1024;

__device__ float g_buf[G_TOTAL];

// ---------------- fast math ----------------
__device__ __forceinline__ float fast_tanh(float x) {
    float y;
    asm("tanh.approx.f32 %0, %1;" : "=f"(y) : "f"(x));
    return y;
}
__device__ __forceinline__ float fast_sigmoid(float x) {
    return 0.5f * fast_tanh(0.5f * x) + 0.5f;
}

// ---------------- task structs ----------------
struct GemmTask {
    const float* base;
    const int*   rowmap;
    const int*   nbrs;
    const float* tbl;
    const float* W;        // [128 x ldw] slice, 128 cols used
    const float* bias;
    float*       out;
    const float* W2;       // optional second pass (same input tile)
    const float* bias2;
    float*       out2;
    int knbr; float invk;
    int ldw, ldo, act;     // act: 0 tanh, 1 relu, 2 none
    int R; int blk0;
};
struct PrepArgs {
    const float *qW, *qb, *kW, *kb, *wW, *embr, *Wih, *bih, *bhh;
    int enable;
};
struct GemmParams { GemmTask t[3]; int nt; PrepArgs prep; };

#define ST_LD 68

__device__ __forceinline__ void g_loadW(float* sW, const float* __restrict__ W, int ldw, int tid)
{
    #pragma unroll
    for (int i = 0; i < 32; i++) {
        int idx = tid + i*128;
        int k = idx >> 5, c4 = idx & 31;
        *(float4*)(sW + k*kD + c4*4) = __ldg((const float4*)(W + (size_t)k*ldw) + c4);
    }
}
__device__ __forceinline__ void g_gemm(const float* __restrict__ sT,
                                       const float* __restrict__ sW,
                                       float acc[8][8], int r0, int c0)
{
    #pragma unroll
    for (int i = 0; i < 8; i++)
        #pragma unroll
        for (int j = 0; j < 8; j++) acc[i][j] = 0.f;
    #pragma unroll 4
    for (int k = 0; k < kD; k++) {
        float4 a0 = *(const float4*)(sT + k*ST_LD + r0);
        float4 a1 = *(const float4*)(sT + k*ST_LD + r0 + 4);
        float4 b0 = *(const float4*)(sW + k*kD + c0);
        float4 b1 = *(const float4*)(sW + k*kD + c0 + 4);
        float av[8] = {a0.x,a0.y,a0.z,a0.w,a1.x,a1.y,a1.z,a1.w};
        float bv[8] = {b0.x,b0.y,b0.z,b0.w,b1.x,b1.y,b1.z,b1.w};
        #pragma unroll
        for (int i = 0; i < 8; i++)
            #pragma unroll
            for (int j = 0; j < 8; j++)
                acc[i][j] += av[i]*bv[j];
    }
}
__device__ __forceinline__ void g_store(const GemmTask& T, float* outp,
                                        const float* __restrict__ bias,
                                        float acc[8][8], int row0, int r0, int c0)
{
    float bsv[8];
    #pragma unroll
    for (int j = 0; j < 8; j++) bsv[j] = (T.act != 2) ? __ldg(&bias[c0 + j]) : 0.f;
    #pragma unroll
    for (int i = 0; i < 8; i++) {
        int gr = row0 + r0 + i;
        if (gr >= T.R) continue;
        float o[8];
        #pragma unroll
        for (int j = 0; j < 8; j++) {
            float v = acc[i][j] + bsv[j];
            if (T.act == 0)      v = fast_tanh(v);
            else if (T.act == 1) v = fmaxf(v, 0.f);
            o[j] = v;
        }
        *(float4*)(outp + (size_t)gr*T.ldo + c0)     = make_float4(o[0],o[1],o[2],o[3]);
        *(float4*)(outp + (size_t)gr*T.ldo + c0 + 4) = make_float4(o[4],o[5],o[6],o[7]);
    }
}

// ---------------- unified GEMM kernel: 128 thr, 64 rows x 128 cols, 8x8 tiles; optional 2nd W-pass ----------------
__global__ __launch_bounds__(128, 2) void gemm_kernel(const GemmParams p)
{
    extern __shared__ float sm[];
    float* sW = sm;             // 128*128
    float* sT = sm + kD*kD;     // 128*68, [k][row]
    const int tid = threadIdx.x;

    if (p.prep.enable && blockIdx.x == (int)gridDim.x - 1) {
        const PrepArgs& A = p.prep;
        float* vec = g_buf + O_V;
        float* rg  = g_buf + O_RG;
        if (tid < kD) {
            float sq = 0.f, sk = 0.f;
            #pragma unroll 4
            for (int j = 0; j < kD; j++) {
                sq += A.qW[tid*kD + j] * A.wW[j];
                sk += A.kW[tid*kD + j] * A.wW[kD + j];
            }
            vec[tid]      = sq;
            vec[kD + tid] = sk;
        }
        if (tid == 0) {
            float s = 0.f;
            for (int j = 0; j < kD; j++) s += A.qb[j] * A.wW[j];
            vec[256] = s;
        }
        if (tid == 1) {
            float s = 0.f;
            for (int j = 0; j < kD; j++) s += A.kb[j] * A.wW[kD + j];
            vec[257] = s;
        }
        for (int c = tid; c < 512; c += 128) {
            for (int r = 0; r < 2; r++) {
                float s = A.bih[c] + A.bhh[c];
                #pragma unroll 4
                for (int k = 0; k < kD; k++)
                    s += A.embr[r*kD + k] * A.Wih[(size_t)(kD + k)*512 + c];
                rg[r*512 + c] = s;
            }
        }
        return;
    }

    int ti = 0;
    #pragma unroll
    for (int i = 1; i < 3; i++)
        if (i < p.nt && (int)blockIdx.x >= p.t[i].blk0) ti = i;
    const GemmTask& T = p.t[ti];
    const int row0 = (blockIdx.x - T.blk0) * 64;

    g_loadW(sW, T.W, T.ldw, tid);

    // gather 64 rows: 2 thr/row, 64 dims (16 float4) each; store TRANSPOSED
    {
        int lr = tid >> 1, part = tid & 1;
        int gr = row0 + lr;
        float4 v[16];
        if (gr < T.R) {
            int src = T.rowmap ? __ldg(&T.rowmap[gr]) : gr;
            const float4* bp = (const float4*)(T.base + (size_t)src*kD) + part*16;
            #pragma unroll
            for (int d = 0; d < 16; d++) v[d] = __ldg(&bp[d]);
            if (T.knbr > 0) {
                float4 s[16];
                #pragma unroll
                for (int d = 0; d < 16; d++) s[d] = make_float4(0.f,0.f,0.f,0.f);
                for (int j = 0; j < T.knbr; j++) {
                    int nb = __ldg(&T.nbrs[(size_t)gr*T.knbr + j]);
                    const float4* tp = (const float4*)(T.tbl + (size_t)nb*kD) + part*16;
                    #pragma unroll
                    for (int d = 0; d < 16; d++) {
                        float4 x = __ldg(&tp[d]);
                        s[d].x += x.x; s[d].y += x.y; s[d].z += x.z; s[d].w += x.w;
                    }
                }
                #pragma unroll
                for (int d = 0; d < 16; d++) {
                    v[d].x += s[d].x * T.invk; v[d].y += s[d].y * T.invk;
                    v[d].z += s[d].z * T.invk; v[d].w += s[d].w * T.invk;
                }
            }
        } else {
            #pragma unroll
            for (int d = 0; d < 16; d++) v[d] = make_float4(0.f,0.f,0.f,0.f);
        }
        #pragma unroll
        for (int d = 0; d < 16; d++) {
            int k0 = part*64 + d*4;
            sT[(k0+0)*ST_LD + lr] = v[d].x;
            sT[(k0+1)*ST_LD + lr] = v[d].y;
            sT[(k0+2)*ST_LD + lr] = v[d].z;
            sT[(k0+3)*ST_LD + lr] = v[d].w;
        }
    }
    __syncthreads();

    const int r0 = (tid >> 4) * 8;
    const int c0 = (tid & 15) * 8;
    float acc[8][8];

    g_gemm(sT, sW, acc, r0, c0);
    g_store(T, T.out, T.bias, acc, row0, r0, c0);

    if (T.W2) {
        __syncthreads();                 // sW reads done
        g_loadW(sW, T.W2, T.ldw, tid);
        __syncthreads();
        g_gemm(sT, sW, acc, r0, c0);
        g_store(T, T.out2, T.bias2, acc, row0, r0, c0);
    }
}

// ---------------- chain3: level2 + last + QTT fused; 98.8 KB smem, 2 blocks/SM ----------------
__global__ __launch_bounds__(128, 2) void chain3_kernel(
    const int* __restrict__ q_nbr,
    const float* __restrict__ aggW, const float* __restrict__ aggb,
    const float* __restrict__ lastW, const float* __restrict__ lastb,
    const float* __restrict__ ftW, const float* __restrict__ ftb)
{
    extern __shared__ float sm[];
    float* sW = sm;                 // 128*128
    float* sT = sm + kD*kD;         // 128*68
    const int tid = threadIdx.x;
    const int row0 = blockIdx.x * 64;

    const float* TB0 = g_buf + O_TB0;
    const float* TB1 = g_buf + O_TB1;
    float* QTT = g_buf + O_TB0;     // in-place

    g_loadW(sW, aggW, kD, tid);

    {
        int lr = tid >> 1, part = tid & 1;
        int gr = row0 + lr;
        float4 v[16];
        if (gr < kNQ) {
            const float4* bp = (const float4*)(TB0 + (size_t)gr*kD) + part*16;
            #pragma unroll
            for (int d = 0; d < 16; d++) v[d] = __ldg(&bp[d]);
            float4 s[16];
            #pragma unroll
            for (int d = 0; d < 16; d++) s[d] = make_float4(0.f,0.f,0.f,0.f);
            #pragma unroll
            for (int j = 0; j < kQN; j++) {
                int nb = __ldg(&q_nbr[(size_t)gr*kQN + j]);
                const float4* tp = (const float4*)(TB1 + (size_t)nb*kD) + part*16;
                #pragma unroll
                for (int d = 0; d < 16; d++) {
                    float4 x = __ldg(&tp[d]);
                    s[d].x += x.x; s[d].y += x.y; s[d].z += x.z; s[d].w += x.w;
                }
            }
            const float iq = 1.f/kQN;
            #pragma unroll
            for (int d = 0; d < 16; d++) {
                v[d].x += s[d].x*iq; v[d].y += s[d].y*iq;
                v[d].z += s[d].z*iq; v[d].w += s[d].w*iq;
            }
        } else {
            #pragma unroll
            for (int d = 0; d < 16; d++) v[d] = make_float4(0.f,0.f,0.f,0.f);
        }
        #pragma unroll
        for (int d = 0; d < 16; d++) {
            int k0 = part*64 + d*4;
            sT[(k0+0)*ST_LD + lr] = v[d].x;
            sT[(k0+1)*ST_LD + lr] = v[d].y;
            sT[(k0+2)*ST_LD + lr] = v[d].z;
            sT[(k0+3)*ST_LD + lr] = v[d].w;
        }
    }
    __syncthreads();

    const int r0 = (tid >> 4) * 8;
    const int c0 = (tid & 15) * 8;
    float acc[8][8];
    float bb[8];

    g_gemm(sT, sW, acc, r0, c0);
    #pragma unroll
    for (int j = 0; j < 8; j++) bb[j] = __ldg(&aggb[c0 + j]);
    __syncthreads();
    #pragma unroll
    for (int i = 0; i < 8; i++)
        #pragma unroll
        for (int j = 0; j < 8; j++)
            sT[(c0+j)*ST_LD + (r0+i)] = fast_tanh(acc[i][j] + bb[j]);
    g_loadW(sW, lastW, kD, tid);
    __syncthreads();

    g_gemm(sT, sW, acc, r0, c0);
    #pragma unroll
    for (int j = 0; j < 8; j++) bb[j] = __ldg(&lastb[c0 + j]);
    __syncthreads();
    #pragma unroll
    for (int i = 0; i < 8; i++)
        #pragma unroll
        for (int j = 0; j < 8; j++)
            sT[(c0+j)*ST_LD + (r0+i)] = fast_tanh(acc[i][j] + bb[j]);
    g_loadW(sW, ftW, kD, tid);
    __syncthreads();

    g_gemm(sT, sW, acc, r0, c0);
    #pragma unroll
    for (int j = 0; j < 8; j++) bb[j] = __ldg(&ftb[c0 + j]);
    #pragma unroll
    for (int i = 0; i < 8; i++) {
        int gr = row0 + r0 + i;
        if (gr >= kNQ) continue;
        float o[8];
        #pragma unroll
        for (int j = 0; j < 8; j++) o[j] = fmaxf(acc[i][j] + bb[j], 0.f);
        *(float4*)(QTT + (size_t)gr*kD + c0)     = make_float4(o[0],o[1],o[2],o[3]);
        *(float4*)(QTT + (size_t)gr*kD + c0 + 4) = make_float4(o[4],o[5],o[6],o[7]);
    }
}

// ---------------- gates3: i/g/o GEMM chain + LSTM epilogue -> Ht + AS (replaces gates+combine) ----------------
__global__ __launch_bounds__(128, 2) void gates3_kernel(
    const int* __restrict__ question, const int* __restrict__ response,
    const float* __restrict__ W_ih)
{
    extern __shared__ float sm[];
    float* sW = sm;
    float* sT = sm + kD*kD;
    const int tid = threadIdx.x;
    const int row0 = blockIdx.x * 64;     // 100 blocks exactly cover 6400 rows

    const float* QTT = g_buf + O_TB0;
    const float* RG  = g_buf + O_RG;
    const float* vec = g_buf + O_V;
    float* Ht = g_buf + O_H;
    float* AS = g_buf + O_AS;

    g_loadW(sW, W_ih, 512, tid);          // i-gate cols

    // gather QTT[question[row]] -> sT (2 thr/row)
    {
        int lr = tid >> 1, part = tid & 1;
        int grow = row0 + lr;
        int q = __ldg(&question[grow]);
        const float4* bp = (const float4*)(QTT + (size_t)q*kD) + part*16;
        #pragma unroll
        for (int d = 0; d < 16; d++) {
            float4 v = __ldg(&bp[d]);
            int k0 = part*64 + d*4;
            sT[(k0+0)*ST_LD + lr] = v.x;
            sT[(k0+1)*ST_LD + lr] = v.y;
            sT[(k0+2)*ST_LD + lr] = v.z;
            sT[(k0+3)*ST_LD + lr] = v.w;
        }
    }
    __syncthreads();

    const int r0 = (tid >> 4) * 8;
    const int c0 = (tid & 15) * 8;
    float acc[8][8];
    float carry[8][8];
    int rr[8];
    #pragma unroll
    for (int i = 0; i < 8; i++) rr[i] = __ldg(&response[row0 + r0 + i]);

    // stage i: sigmoid(i + RGi) -> carry
    g_gemm(sT, sW, acc, r0, c0);
    #pragma unroll
    for (int i = 0; i < 8; i++)
        #pragma unroll
        for (int j = 0; j < 8; j++)
            carry[i][j] = fast_sigmoid(acc[i][j] + RG[rr[i]*512 + c0 + j]);
    __syncthreads();
    g_loadW(sW, W_ih + 256, 512, tid);    // g-gate cols
    __syncthreads();

    // stage g: carry = tanh( carry * tanh(g + RGg) )
    g_gemm(sT, sW, acc, r0, c0);
    #pragma unroll
    for (int i = 0; i < 8; i++)
        #pragma unroll
        for (int j = 0; j < 8; j++)
            carry[i][j] = fast_tanh(carry[i][j] * fast_tanh(acc[i][j] + RG[rr[i]*512 + 256 + c0 + j]));
    __syncthreads();
    g_loadW(sW, W_ih + 384, 512, tid);    // o-gate cols
    __syncthreads();

    // stage o: h = sigmoid(o + RGo) * carry -> Ht + AS
    g_gemm(sT, sW, acc, r0, c0);
    float qv[8];
    #pragma unroll
    for (int j = 0; j < 8; j++) qv[j] = vec[c0 + j];
    const float cq = vec[256];

    #pragma unroll
    for (int i = 0; i < 8; i++) {
        int grow = row0 + r0 + i;
        int b = grow / kS, s = grow % kS;
        float p = 0.f;
        #pragma unroll
        for (int j = 0; j < 8; j++) {
            float hv = fast_sigmoid(acc[i][j] + RG[rr[i]*512 + 384 + c0 + j]) * carry[i][j];
            Ht[((size_t)b*kD + c0 + j)*kS + s] = hv;
            p += hv * qv[j];
        }
        // reduce over 16 threads (lanes tid&15) sharing this row
        p += __shfl_down_sync(0xffffffffu, p, 8, 16);
        p += __shfl_down_sync(0xffffffffu, p, 4, 16);
        p += __shfl_down_sync(0xffffffffu, p, 2, 16);
        p += __shfl_down_sync(0xffffffffu, p, 1, 16);
        if ((tid & 15) == 0 && s < kT)
            AS[b*kT + s] = p + cq;
    }
}

// ---------------- pred: one warp per (b,t); lane owns 4 consecutive n; exact-quad striding ----------------
__global__ __launch_bounds__(32, 24) void pred_kernel(
    const int* __restrict__ question,
    const int* __restrict__ qs_skills,
    const float* __restrict__ emb_q,
    const float* __restrict__ emb_s,
    float* __restrict__ out)
{
    const float* Ht  = g_buf + O_H;
    const float* as  = g_buf + O_AS;
    const float* vec = g_buf + O_V;

    __shared__ __align__(16) float sqs[5][kD];

    const int t = kT - 1 - blockIdx.x;     // big t first
    const int b = blockIdx.y;
    const int lane = threadIdx.x;

    int q = __ldg(&question[b*kS + t + 1]);
    ((float4*)sqs[0])[lane] = __ldg((const float4*)(emb_q + (size_t)q*kD) + lane);
    #pragma unroll
    for (int m = 1; m < 5; m++) {
        int si = __ldg(&qs_skills[q*4 + m - 1]);
        ((float4*)sqs[m])[lane] = __ldg((const float4*)(emb_s + (size_t)si*kD) + lane);
    }
    __syncwarp();

    float4 kv4 = *((const float4*)(vec + kD) + lane);
    float r[5];
    #pragma unroll
    for (int m = 0; m < 5; m++) {
        float4 s4 = ((float4*)sqs[m])[lane];
        float p = s4.x*kv4.x + s4.y*kv4.y + s4.z*kv4.z + s4.w*kv4.w;
        #pragma unroll
        for (int o = 16; o; o >>= 1) p += __shfl_xor_sync(0xffffffffu, p, o);
        r[m] = p;
    }
    {
        float mx = r[0];
        #pragma unroll
        for (int m = 1; m < 5; m++) mx = fmaxf(mx, r[m]);
        float se = 0.f;
        #pragma unroll
        for (int m = 0; m < 5; m++) { r[m] = __expf(r[m] - mx); se += r[m]; }
        float inv = __frcp_rn(se);
        #pragma unroll
        for (int m = 0; m < 5; m++) r[m] *= inv;
    }

    const float* asb = as + b*kT;

    float M1 = -1e30f;
    for (int n = lane; n <= t; n += 32) M1 = fmaxf(M1, asb[n]);
    #pragma unroll
    for (int o = 16; o; o >>= 1) M1 = fmaxf(M1, __shfl_xor_sync(0xffffffffu, M1, o));

    const float* hb = Ht + (size_t)b*kD*kS;
    float sum_v = 0.f, sum_e = 0.f;

    const int nquads = (t >> 2) + 1;
    for (int qi = lane; qi < nquads; qi += 32) {
        const int n0 = qi * 4;
        const float* hcol = hb + n0;
        float a0[4] = {0.f,0.f,0.f,0.f};
        float a1[4] = {0.f,0.f,0.f,0.f};
        float a2[4] = {0.f,0.f,0.f,0.f};
        float a3[4] = {0.f,0.f,0.f,0.f};
        float a4[4] = {0.f,0.f,0.f,0.f};

        #pragma unroll 2
        for (int d = 0; d < kD; d += 4) {
            float4 s0 = *(const float4*)&sqs[0][d];
            float4 s1 = *(const float4*)&sqs[1][d];
            float4 s2 = *(const float4*)&sqs[2][d];
            float4 s3 = *(const float4*)&sqs[3][d];
            float4 s4 = *(const float4*)&sqs[4][d];
            #pragma unroll
            for (int dd = 0; dd < 4; dd++) {
                float4 hv = *(const float4*)(hcol + (size_t)(d + dd)*kS);
                float c0v = (&s0.x)[dd];
                float c1v = (&s1.x)[dd];
                float c2v = (&s2.x)[dd];
                float c3v = (&s3.x)[dd];
                float c4v = (&s4.x)[dd];
                a0[0] += hv.x*c0v; a0[1] += hv.y*c0v; a0[2] += hv.z*c0v; a0[3] += hv.w*c0v;
                a1[0] += hv.x*c1v; a1[1] += hv.y*c1v; a1[2] += hv.z*c1v; a1[3] += hv.w*c1v;
                a2[0] += hv.x*c2v; a2[1] += hv.y*c2v; a2[2] += hv.z*c2v; a2[3] += hv.w*c2v;
                a3[0] += hv.x*c3v; a3[1] += hv.y*c3v; a3[2] += hv.z*c3v; a3[3] += hv.w*c3v;
                a4[0] += hv.x*c4v; a4[1] += hv.y*c4v; a4[2] += hv.z*c4v; a4[3] += hv.w*c4v;
            }
        }

        #pragma unroll
        for (int j = 0; j < 4; j++) {
            int n = n0 + j;
            if (n <= t) {
                float e = __expf(asb[n] - M1);
                float sv = r[0]*fast_sigmoid(a0[j]) + r[1]*fast_sigmoid(a1[j])
                         + r[2]*fast_sigmoid(a2[j]) + r[3]*fast_sigmoid(a3[j])
                         + r[4]*fast_sigmoid(a4[j]);
                sum_v += e * sv;
                sum_e += e;
            }
        }
    }
    #pragma unroll
    for (int o = 16; o; o >>= 1) {
        sum_v += __shfl_xor_sync(0xffffffffu, sum_v, o);
        sum_e += __shfl_xor_sync(0xffffffffu, sum_e, o);
    }
    if (lane == 0) {
        out[b*kS + t + 1] = sum_v / sum_e;
        if (t == 0) out[b*kS] = 0.f;
    }
}

// ---------------- launch ----------------
extern "C" void kernel_launch(void* const* d_in, const int* in_sizes, int n_in,
                              void* d_out, int out_size)
{
    const int*   question = (const int*)  d_in[0];
    const int*   response = (const int*)  d_in[1];
    const int*   q_nbr    = (const int*)  d_in[3];
    const int*   s_nbr    = (const int*)  d_in[4];
    const int*   qs_sk    = (const int*)  d_in[5];
    const float* emb_q    = (const float*)d_in[6];
    const float* emb_s    = (const float*)d_in[7];
    const float* emb_r    = (const float*)d_in[8];
    const float* W_ih     = (const float*)d_in[9];
    const float* b_ih     = (const float*)d_in[10];
    const float* b_hh     = (const float*)d_in[11];
    const float* ft_W     = (const float*)d_in[12];
    const float* ft_b     = (const float*)d_in[13];
    const float* agg_W    = (const float*)d_in[14];
    const float* agg_b    = (const float*)d_in[15];
    const float* last_W   = (const float*)d_in[16];
    const float* last_b   = (const float*)d_in[17];
    const float* q_W      = (const float*)d_in[18];
    const float* q_b      = (const float*)d_in[19];
    const float* k_W      = (const float*)d_in[20];
    const float* k_b      = (const float*)d_in[21];
    const float* w_W      = (const float*)d_in[22];
    float* out = (float*)d_out;

    float* buf = nullptr;
    cudaGetSymbolAddress((void**)&buf, g_buf);
    float* TA0 = buf + O_TA0;
    float* TA1 = buf + O_TA1;
    float* TA2 = buf + O_TA2;
    float* TB0 = buf + O_TB0;
    float* TB1 = buf + O_TB1;

    const int GEMM_SMEM = (kD*kD + kD*ST_LD) * (int)sizeof(float);   // ~100 KB
    static bool attr_done = false;
    if (!attr_done) {
        cudaFuncSetAttribute(gemm_kernel,   cudaFuncAttributeMaxDynamicSharedMemorySize, GEMM_SMEM);
        cudaFuncSetAttribute(chain3_kernel, cudaFuncAttributeMaxDynamicSharedMemorySize, GEMM_SMEM);
        cudaFuncSetAttribute(gates3_kernel, cudaFuncAttributeMaxDynamicSharedMemorySize, GEMM_SMEM);
        attr_done = true;
    }

    const int gq = (kNQ + 63) / 64;    // 157
    const int gs = (kNS + 63) / 64;    // 8
    const float iq = 1.f/kQN, is = 1.f/kSN;

    PrepArgs noprep = {}; noprep.enable = 0;

    // level 0: one dual task (TA0+TA2, shared gather) + TA1 + prep = 166 blocks (one wave)
    {
        GemmParams p;
        p.nt = 2;
        p.t[0] = { emb_q, nullptr, q_nbr, emb_s, agg_W,         agg_b,       TA0,
                   agg_W + 2*16384, agg_b + 256, TA2,
                   kQN, iq, kD, kD, 0, kNQ, 0 };
        p.t[1] = { emb_s, nullptr, s_nbr, emb_q, agg_W + 16384, agg_b + 128, TA1,
                   nullptr, nullptr, nullptr,
                   kSN, is, kD, kD, 0, kNS, gq };
        p.t[2] = p.t[1];
        p.prep = { q_W, q_b, k_W, k_b, w_W, emb_r, W_ih, b_ih, b_hh, 1 };
        gemm_kernel<<<gq + gs + 1, 128, GEMM_SMEM>>>(p);
    }
    // level 1: TB0, TB1
    {
        GemmParams p;
        p.nt = 2;
        p.t[0] = { TA0, nullptr, q_nbr, TA1, agg_W,         agg_b,       TB0,
                   nullptr, nullptr, nullptr, kQN, iq, kD, kD, 0, kNQ, 0 };
        p.t[1] = { TA1, nullptr, s_nbr, TA2, agg_W + 16384, agg_b + 128, TB1,
                   nullptr, nullptr, nullptr, kSN, is, kD, kD, 0, kNS, gq };
        p.t[2] = p.t[1];
        p.prep = noprep;
        gemm_kernel<<<gq + gs, 128, GEMM_SMEM>>>(p);
    }
    // level2 + last + QTT fused
    chain3_kernel<<<gq, 128, GEMM_SMEM>>>(q_nbr, agg_W, agg_b, last_W, last_b, ft_W, ft_b);

    // gates + LSTM combine fused -> Ht + AS
    gates3_kernel<<<(kB*kS)/64, 128, GEMM_SMEM>>>(question, response, W_ih);

    dim3 pg(kT, kB);
    pred_kernel<<<pg, 32>>>(question, qs_sk, emb_q, emb_s, out);
}

// round 16
// speedup vs baseline: 1.0680x; 1.0680x over previous
#include <cuda_runtime.h>
#include <math.h>
#include <stdint.h>

// ---------------- problem constants ----------------
#define kNQ 10000
#define kNS 500
#define kQN 4
#define kSN 10
#define kB  32
#define kS  200
#define kD  128
#define kT  199   // S-1

// ---------------- scratch layout (floats) ----------------
__host__ __device__ constexpr size_t O_TA0 = 0;                        // reused: G
__host__ __device__ constexpr size_t O_TA1 = O_TA0 + (size_t)kNQ*kD;
__host__ __device__ constexpr size_t O_TA2 = O_TA1 + (size_t)kNS*kD;
__host__ __device__ constexpr size_t O_TB0 = O_TA2 + (size_t)kNQ*kD;   // reused: QTT
__host__ __device__ constexpr size_t O_TB1 = O_TB0 + (size_t)kNQ*kD;
__host__ __device__ constexpr size_t O_A   = O_TB1 + (size_t)kNS*kD;   // spare
__host__ __device__ constexpr size_t O_H   = O_A   + (size_t)kNQ*kD;  // Ht: [b][d][s]
__host__ __device__ constexpr size_t O_AS  = O_H   + (size_t)kB*kS*kD;
__host__ __device__ constexpr size_t O_V   = O_AS  + (size_t)kB*kT;   // qv[128], kv[128], c_q, c_k
__host__ __device__ constexpr size_t O_RG  = O_V   + 258;             // r_gates 2x512
__host__ __device__ constexpr size_t G_TOTAL = O_RG + 1024;

__device__ float g_buf[G_TOTAL];

// ---------------- fast math ----------------
__device__ __forceinline__ float fast_tanh(float x) {
    float y;
    asm("tanh.approx.f32 %0, %1;" : "=f"(y) : "f"(x));
    return y;
}
__device__ __forceinline__ float fast_sigmoid(float x) {
    return 0.5f * fast_tanh(0.5f * x) + 0.5f;
}

// ---------------- task structs ----------------
struct GemmTask {
    const float* base;
    const int*   rowmap;
    const int*   nbrs;
    const float* tbl;
    const float* W;        // [128 x ldw] slice, 128 cols used
    const float* bias;
    float*       out;
    const float* W2;       // optional second pass (same input tile)
    const float* bias2;
    float*       out2;
    int knbr; float invk;
    int ldw, ldo, act;     // act: 0 tanh, 1 relu, 2 none
    int R; int blk0;
};
struct PrepArgs {
    const float *qW, *qb, *kW, *kb, *wW, *embr, *Wih, *bih, *bhh;
    int enable;
};
struct GemmParams { GemmTask t[3]; int nt; PrepArgs prep; };

#define ST_LD 68

__device__ __forceinline__ void g_loadW(float* sW, const float* __restrict__ W, int ldw, int tid)
{
    #pragma unroll
    for (int i = 0; i < 32; i++) {
        int idx = tid + i*128;
        int k = idx >> 5, c4 = idx & 31;
        *(float4*)(sW + k*kD + c4*4) = __ldg((const float4*)(W + (size_t)k*ldw) + c4);
    }
}
__device__ __forceinline__ void g_gemm(const float* __restrict__ sT,
                                       const float* __restrict__ sW,
                                       float acc[8][8], int r0, int c0)
{
    #pragma unroll
    for (int i = 0; i < 8; i++)
        #pragma unroll
        for (int j = 0; j < 8; j++) acc[i][j] = 0.f;
    #pragma unroll 4
    for (int k = 0; k < kD; k++) {
        float4 a0 = *(const float4*)(sT + k*ST_LD + r0);
        float4 a1 = *(const float4*)(sT + k*ST_LD + r0 + 4);
        float4 b0 = *(const float4*)(sW + k*kD + c0);
        float4 b1 = *(const float4*)(sW + k*kD + c0 + 4);
        float av[8] = {a0.x,a0.y,a0.z,a0.w,a1.x,a1.y,a1.z,a1.w};
        float bv[8] = {b0.x,b0.y,b0.z,b0.w,b1.x,b1.y,b1.z,b1.w};
        #pragma unroll
        for (int i = 0; i < 8; i++)
            #pragma unroll
            for (int j = 0; j < 8; j++)
                acc[i][j] += av[i]*bv[j];
    }
}
__device__ __forceinline__ void g_store(const GemmTask& T, float* outp,
                                        const float* __restrict__ bias,
                                        float acc[8][8], int row0, int r0, int c0)
{
    float bsv[8];
    #pragma unroll
    for (int j = 0; j < 8; j++) bsv[j] = (T.act != 2) ? __ldg(&bias[c0 + j]) : 0.f;
    #pragma unroll
    for (int i = 0; i < 8; i++) {
        int gr = row0 + r0 + i;
        if (gr >= T.R) continue;
        float o[8];
        #pragma unroll
        for (int j = 0; j < 8; j++) {
            float v = acc[i][j] + bsv[j];
            if (T.act == 0)      v = fast_tanh(v);
            else if (T.act == 1) v = fmaxf(v, 0.f);
            o[j] = v;
        }
        *(float4*)(outp + (size_t)gr*T.ldo + c0)     = make_float4(o[0],o[1],o[2],o[3]);
        *(float4*)(outp + (size_t)gr*T.ldo + c0 + 4) = make_float4(o[4],o[5],o[6],o[7]);
    }
}

// ---------------- unified GEMM kernel: 128 thr, 64 rows x 128 cols, 8x8 tiles; optional 2nd W-pass ----------------
__global__ __launch_bounds__(128, 2) void gemm_kernel(const GemmParams p)
{
    extern __shared__ float sm[];
    float* sW = sm;             // 128*128
    float* sT = sm + kD*kD;     // 128*68, [k][row]
    const int tid = threadIdx.x;

    if (p.prep.enable && blockIdx.x == (int)gridDim.x - 1) {
        const PrepArgs& A = p.prep;
        float* vec = g_buf + O_V;
        float* rg  = g_buf + O_RG;
        if (tid < kD) {
            float sq = 0.f, sk = 0.f;
            #pragma unroll 4
            for (int j = 0; j < kD; j++) {
                sq += A.qW[tid*kD + j] * A.wW[j];
                sk += A.kW[tid*kD + j] * A.wW[kD + j];
            }
            vec[tid]      = sq;
            vec[kD + tid] = sk;
        }
        if (tid == 0) {
            float s = 0.f;
            for (int j = 0; j < kD; j++) s += A.qb[j] * A.wW[j];
            vec[256] = s;
        }
        if (tid == 1) {
            float s = 0.f;
            for (int j = 0; j < kD; j++) s += A.kb[j] * A.wW[kD + j];
            vec[257] = s;
        }
        for (int c = tid; c < 512; c += 128) {
            for (int r = 0; r < 2; r++) {
                float s = A.bih[c] + A.bhh[c];
                #pragma unroll 4
                for (int k = 0; k < kD; k++)
                    s += A.embr[r*kD + k] * A.Wih[(size_t)(kD + k)*512 + c];
                rg[r*512 + c] = s;
            }
        }
        return;
    }

    int ti = 0;
    #pragma unroll
    for (int i = 1; i < 3; i++)
        if (i < p.nt && (int)blockIdx.x >= p.t[i].blk0) ti = i;
    const GemmTask& T = p.t[ti];
    const int row0 = (blockIdx.x - T.blk0) * 64;

    g_loadW(sW, T.W, T.ldw, tid);

    // gather 64 rows: 2 thr/row, 64 dims (16 float4) each; store TRANSPOSED
    {
        int lr = tid >> 1, part = tid & 1;
        int gr = row0 + lr;
        float4 v[16];
        if (gr < T.R) {
            int src = T.rowmap ? __ldg(&T.rowmap[gr]) : gr;
            const float4* bp = (const float4*)(T.base + (size_t)src*kD) + part*16;
            #pragma unroll
            for (int d = 0; d < 16; d++) v[d] = __ldg(&bp[d]);
            if (T.knbr > 0) {
                float4 s[16];
                #pragma unroll
                for (int d = 0; d < 16; d++) s[d] = make_float4(0.f,0.f,0.f,0.f);
                for (int j = 0; j < T.knbr; j++) {
                    int nb = __ldg(&T.nbrs[(size_t)gr*T.knbr + j]);
                    const float4* tp = (const float4*)(T.tbl + (size_t)nb*kD) + part*16;
                    #pragma unroll
                    for (int d = 0; d < 16; d++) {
                        float4 x = __ldg(&tp[d]);
                        s[d].x += x.x; s[d].y += x.y; s[d].z += x.z; s[d].w += x.w;
                    }
                }
                #pragma unroll
                for (int d = 0; d < 16; d++) {
                    v[d].x += s[d].x * T.invk; v[d].y += s[d].y * T.invk;
                    v[d].z += s[d].z * T.invk; v[d].w += s[d].w * T.invk;
                }
            }
        } else {
            #pragma unroll
            for (int d = 0; d < 16; d++) v[d] = make_float4(0.f,0.f,0.f,0.f);
        }
        #pragma unroll
        for (int d = 0; d < 16; d++) {
            int k0 = part*64 + d*4;
            sT[(k0+0)*ST_LD + lr] = v[d].x;
            sT[(k0+1)*ST_LD + lr] = v[d].y;
            sT[(k0+2)*ST_LD + lr] = v[d].z;
            sT[(k0+3)*ST_LD + lr] = v[d].w;
        }
    }
    __syncthreads();

    const int r0 = (tid >> 4) * 8;
    const int c0 = (tid & 15) * 8;
    float acc[8][8];

    g_gemm(sT, sW, acc, r0, c0);
    g_store(T, T.out, T.bias, acc, row0, r0, c0);

    if (T.W2) {
        __syncthreads();                 // sW reads done
        g_loadW(sW, T.W2, T.ldw, tid);
        __syncthreads();
        g_gemm(sT, sW, acc, r0, c0);
        g_store(T, T.out2, T.bias2, acc, row0, r0, c0);
    }
}

// ---------------- chain3: level2 + last + QTT fused; 98.8 KB smem, 2 blocks/SM ----------------
__global__ __launch_bounds__(128, 2) void chain3_kernel(
    const int* __restrict__ q_nbr,
    const float* __restrict__ aggW, const float* __restrict__ aggb,
    const float* __restrict__ lastW, const float* __restrict__ lastb,
    const float* __restrict__ ftW, const float* __restrict__ ftb)
{
    extern __shared__ float sm[];
    float* sW = sm;                 // 128*128
    float* sT = sm + kD*kD;         // 128*68
    const int tid = threadIdx.x;
    const int row0 = blockIdx.x * 64;

    const float* TB0 = g_buf + O_TB0;
    const float* TB1 = g_buf + O_TB1;
    float* QTT = g_buf + O_TB0;     // in-place

    g_loadW(sW, aggW, kD, tid);

    {
        int lr = tid >> 1, part = tid & 1;
        int gr = row0 + lr;
        float4 v[16];
        if (gr < kNQ) {
            const float4* bp = (const float4*)(TB0 + (size_t)gr*kD) + part*16;
            #pragma unroll
            for (int d = 0; d < 16; d++) v[d] = __ldg(&bp[d]);
            float4 s[16];
            #pragma unroll
            for (int d = 0; d < 16; d++) s[d] = make_float4(0.f,0.f,0.f,0.f);
            #pragma unroll
            for (int j = 0; j < kQN; j++) {
                int nb = __ldg(&q_nbr[(size_t)gr*kQN + j]);
                const float4* tp = (const float4*)(TB1 + (size_t)nb*kD) + part*16;
                #pragma unroll
                for (int d = 0; d < 16; d++) {
                    float4 x = __ldg(&tp[d]);
                    s[d].x += x.x; s[d].y += x.y; s[d].z += x.z; s[d].w += x.w;
                }
            }
            const float iq = 1.f/kQN;
            #pragma unroll
            for (int d = 0; d < 16; d++) {
                v[d].x += s[d].x*iq; v[d].y += s[d].y*iq;
                v[d].z += s[d].z*iq; v[d].w += s[d].w*iq;
            }
        } else {
            #pragma unroll
            for (int d = 0; d < 16; d++) v[d] = make_float4(0.f,0.f,0.f,0.f);
        }
        #pragma unroll
        for (int d = 0; d < 16; d++) {
            int k0 = part*64 + d*4;
            sT[(k0+0)*ST_LD + lr] = v[d].x;
            sT[(k0+1)*ST_LD + lr] = v[d].y;
            sT[(k0+2)*ST_LD + lr] = v[d].z;
            sT[(k0+3)*ST_LD + lr] = v[d].w;
        }
    }
    __syncthreads();

    const int r0 = (tid >> 4) * 8;
    const int c0 = (tid & 15) * 8;
    float acc[8][8];
    float bb[8];

    g_gemm(sT, sW, acc, r0, c0);
    #pragma unroll
    for (int j = 0; j < 8; j++) bb[j] = __ldg(&aggb[c0 + j]);
    __syncthreads();
    #pragma unroll
    for (int i = 0; i < 8; i++)
        #pragma unroll
        for (int j = 0; j < 8; j++)
            sT[(c0+j)*ST_LD + (r0+i)] = fast_tanh(acc[i][j] + bb[j]);
    g_loadW(sW, lastW, kD, tid);
    __syncthreads();

    g_gemm(sT, sW, acc, r0, c0);
    #pragma unroll
    for (int j = 0; j < 8; j++) bb[j] = __ldg(&lastb[c0 + j]);
    __syncthreads();
    #pragma unroll
    for (int i = 0; i < 8; i++)
        #pragma unroll
        for (int j = 0; j < 8; j++)
            sT[(c0+j)*ST_LD + (r0+i)] = fast_tanh(acc[i][j] + bb[j]);
    g_loadW(sW, ftW, kD, tid);
    __syncthreads();

    g_gemm(sT, sW, acc, r0, c0);
    #pragma unroll
    for (int j = 0; j < 8; j++) bb[j] = __ldg(&ftb[c0 + j]);
    #pragma unroll
    for (int i = 0; i < 8; i++) {
        int gr = row0 + r0 + i;
        if (gr >= kNQ) continue;
        float o[8];
        #pragma unroll
        for (int j = 0; j < 8; j++) o[j] = fmaxf(acc[i][j] + bb[j], 0.f);
        *(float4*)(QTT + (size_t)gr*kD + c0)     = make_float4(o[0],o[1],o[2],o[3]);
        *(float4*)(QTT + (size_t)gr*kD + c0 + 4) = make_float4(o[4],o[5],o[6],o[7]);
    }
}

// ---------------- combine: G (i|g|o raw) + RG -> h -> Ht transposed + AS ----------------
__global__ __launch_bounds__(256, 4) void combine_kernel(const int* __restrict__ response)
{
    const float* G   = g_buf + O_TA0;   // [6400][384]
    const float* RG  = g_buf + O_RG;
    const float* vec = g_buf + O_V;
    float* Ht = g_buf + O_H;
    float* AS = g_buf + O_AS;

    const int tid = threadIdx.x;
    const int row = blockIdx.x * 16 + (tid >> 4);
    const int d0  = (tid & 15) * 8;
    const int rr  = __ldg(&response[row]);
    const int b = row / kS, s = row % kS;
    const float* gp = G + (size_t)row*384;

    float hv[8];
    float pacc = 0.f;
    #pragma unroll
    for (int jj = 0; jj < 2; jj++) {
        float4 gi = *(const float4*)(gp + d0 + jj*4);
        float4 gg = *(const float4*)(gp + 128 + d0 + jj*4);
        float4 go = *(const float4*)(gp + 256 + d0 + jj*4);
        float iv4[4] = {gi.x,gi.y,gi.z,gi.w};
        float gv4[4] = {gg.x,gg.y,gg.z,gg.w};
        float ov4[4] = {go.x,go.y,go.z,go.w};
        #pragma unroll
        for (int e = 0; e < 4; e++) {
            int j = jj*4 + e;
            float iv = fast_sigmoid(iv4[e] + RG[rr*512 + d0 + j]);
            float gv = fast_tanh   (gv4[e] + RG[rr*512 + 256 + d0 + j]);
            float ov = fast_sigmoid(ov4[e] + RG[rr*512 + 384 + d0 + j]);
            hv[j] = ov * fast_tanh(iv * gv);
            pacc += hv[j] * vec[d0 + j];
        }
    }
    #pragma unroll
    for (int j = 0; j < 8; j++)
        Ht[((size_t)b*kD + d0 + j)*kS + s] = hv[j];

    pacc += __shfl_down_sync(0xffffffffu, pacc, 8, 16);
    pacc += __shfl_down_sync(0xffffffffu, pacc, 4, 16);
    pacc += __shfl_down_sync(0xffffffffu, pacc, 2, 16);
    pacc += __shfl_down_sync(0xffffffffu, pacc, 1, 16);
    if ((tid & 15) == 0 && s < kT)
        AS[b*kT + s] = pacc + vec[256];
}

// ---------------- pred: one warp per (b,t); lane owns 4 consecutive n; exact-quad striding ----------------
__global__ __launch_bounds__(32, 24) void pred_kernel(
    const int* __restrict__ question,
    const int* __restrict__ qs_skills,
    const float* __restrict__ emb_q,
    const float* __restrict__ emb_s,
    float* __restrict__ out)
{
    const float* Ht  = g_buf + O_H;
    const float* as  = g_buf + O_AS;
    const float* vec = g_buf + O_V;

    __shared__ __align__(16) float sqs[5][kD];

    const int t = kT - 1 - blockIdx.x;     // big t first
    const int b = blockIdx.y;
    const int lane = threadIdx.x;

    int q = __ldg(&question[b*kS + t + 1]);
    ((float4*)sqs[0])[lane] = __ldg((const float4*)(emb_q + (size_t)q*kD) + lane);
    #pragma unroll
    for (int m = 1; m < 5; m++) {
        int si = __ldg(&qs_skills[q*4 + m - 1]);
        ((float4*)sqs[m])[lane] = __ldg((const float4*)(emb_s + (size_t)si*kD) + lane);
    }
    __syncwarp();

    float4 kv4 = *((const float4*)(vec + kD) + lane);
    float r[5];
    #pragma unroll
    for (int m = 0; m < 5; m++) {
        float4 s4 = ((float4*)sqs[m])[lane];
        float p = s4.x*kv4.x + s4.y*kv4.y + s4.z*kv4.z + s4.w*kv4.w;
        #pragma unroll
        for (int o = 16; o; o >>= 1) p += __shfl_xor_sync(0xffffffffu, p, o);
        r[m] = p;
    }
    {
        float mx = r[0];
        #pragma unroll
        for (int m = 1; m < 5; m++) mx = fmaxf(mx, r[m]);
        float se = 0.f;
        #pragma unroll
        for (int m = 0; m < 5; m++) { r[m] = __expf(r[m] - mx); se += r[m]; }
        float inv = __frcp_rn(se);
        #pragma unroll
        for (int m = 0; m < 5; m++) r[m] *= inv;
    }

    const float* asb = as + b*kT;

    float M1 = -1e30f;
    for (int n = lane; n <= t; n += 32) M1 = fmaxf(M1, asb[n]);
    #pragma unroll
    for (int o = 16; o; o >>= 1) M1 = fmaxf(M1, __shfl_xor_sync(0xffffffffu, M1, o));

    const float* hb = Ht + (size_t)b*kD*kS;
    float sum_v = 0.f, sum_e = 0.f;

    const int nquads = (t >> 2) + 1;
    for (int qi = lane; qi < nquads; qi += 32) {
        const int n0 = qi * 4;
        const float* hcol = hb + n0;
        float a0[4] = {0.f,0.f,0.f,0.f};
        float a1[4] = {0.f,0.f,0.f,0.f};
        float a2[4] = {0.f,0.f,0.f,0.f};
        float a3[4] = {0.f,0.f,0.f,0.f};
        float a4[4] = {0.f,0.f,0.f,0.f};

        #pragma unroll 2
        for (int d = 0; d < kD; d += 4) {
            float4 s0 = *(const float4*)&sqs[0][d];
            float4 s1 = *(const float4*)&sqs[1][d];
            float4 s2 = *(const float4*)&sqs[2][d];
            float4 s3 = *(const float4*)&sqs[3][d];
            float4 s4 = *(const float4*)&sqs[4][d];
            #pragma unroll
            for (int dd = 0; dd < 4; dd++) {
                float4 hv = *(const float4*)(hcol + (size_t)(d + dd)*kS);
                float c0v = (&s0.x)[dd];
                float c1v = (&s1.x)[dd];
                float c2v = (&s2.x)[dd];
                float c3v = (&s3.x)[dd];
                float c4v = (&s4.x)[dd];
                a0[0] += hv.x*c0v; a0[1] += hv.y*c0v; a0[2] += hv.z*c0v; a0[3] += hv.w*c0v;
                a1[0] += hv.x*c1v; a1[1] += hv.y*c1v; a1[2] += hv.z*c1v; a1[3] += hv.w*c1v;
                a2[0] += hv.x*c2v; a2[1] += hv.y*c2v; a2[2] += hv.z*c2v; a2[3] += hv.w*c2v;
                a3[0] += hv.x*c3v; a3[1] += hv.y*c3v; a3[2] += hv.z*c3v; a3[3] += hv.w*c3v;
                a4[0] += hv.x*c4v; a4[1] += hv.y*c4v; a4[2] += hv.z*c4v; a4[3] += hv.w*c4v;
            }
        }

        #pragma unroll
        for (int j = 0; j < 4; j++) {
            int n = n0 + j;
            if (n <= t) {
                float e = __expf(asb[n] - M1);
                float sv = r[0]*fast_sigmoid(a0[j]) + r[1]*fast_sigmoid(a1[j])
                         + r[2]*fast_sigmoid(a2[j]) + r[3]*fast_sigmoid(a3[j])
                         + r[4]*fast_sigmoid(a4[j]);
                sum_v += e * sv;
                sum_e += e;
            }
        }
    }
    #pragma unroll
    for (int o = 16; o; o >>= 1) {
        sum_v += __shfl_xor_sync(0xffffffffu, sum_v, o);
        sum_e += __shfl_xor_sync(0xffffffffu, sum_e, o);
    }
    if (lane == 0) {
        out[b*kS + t + 1] = sum_v / sum_e;
        if (t == 0) out[b*kS] = 0.f;
    }
}

// ---------------- launch ----------------
extern "C" void kernel_launch(void* const* d_in, const int* in_sizes, int n_in,
                              void* d_out, int out_size)
{
    const int*   question = (const int*)  d_in[0];
    const int*   response = (const int*)  d_in[1];
    const int*   q_nbr    = (const int*)  d_in[3];
    const int*   s_nbr    = (const int*)  d_in[4];
    const int*   qs_sk    = (const int*)  d_in[5];
    const float* emb_q    = (const float*)d_in[6];
    const float* emb_s    = (const float*)d_in[7];
    const float* emb_r    = (const float*)d_in[8];
    const float* W_ih     = (const float*)d_in[9];
    const float* b_ih     = (const float*)d_in[10];
    const float* b_hh     = (const float*)d_in[11];
    const float* ft_W     = (const float*)d_in[12];
    const float* ft_b     = (const float*)d_in[13];
    const float* agg_W    = (const float*)d_in[14];
    const float* agg_b    = (const float*)d_in[15];
    const float* last_W   = (const float*)d_in[16];
    const float* last_b   = (const float*)d_in[17];
    const float* q_W      = (const float*)d_in[18];
    const float* q_b      = (const float*)d_in[19];
    const float* k_W      = (const float*)d_in[20];
    const float* k_b      = (const float*)d_in[21];
    const float* w_W      = (const float*)d_in[22];
    float* out = (float*)d_out;

    float* buf = nullptr;
    cudaGetSymbolAddress((void**)&buf, g_buf);
    float* TA0 = buf + O_TA0;
    float* TA1 = buf + O_TA1;
    float* TA2 = buf + O_TA2;
    float* TB0 = buf + O_TB0;
    float* TB1 = buf + O_TB1;
    float* QTT = buf + O_TB0;   // chain3 writes QTT in place of TB0
    float* G   = buf + O_TA0;   // gates scratch; TA0/TA1/TA2 dead after L1

    const int GEMM_SMEM = (kD*kD + kD*ST_LD) * (int)sizeof(float);   // ~100 KB
    static bool attr_done = false;
    if (!attr_done) {
        cudaFuncSetAttribute(gemm_kernel,   cudaFuncAttributeMaxDynamicSharedMemorySize, GEMM_SMEM);
        cudaFuncSetAttribute(chain3_kernel, cudaFuncAttributeMaxDynamicSharedMemorySize, GEMM_SMEM);
        attr_done = true;
    }

    const int gq = (kNQ + 63) / 64;    // 157
    const int gs = (kNS + 63) / 64;    // 8
    const int gr = (kB*kS) / 64;       // 100
    const float iq = 1.f/kQN, is = 1.f/kSN;

    PrepArgs noprep = {}; noprep.enable = 0;

    // level 0: one dual task (TA0+TA2, shared gather) + TA1 + prep = 166 blocks (one wave)
    {
        GemmParams p;
        p.nt = 2;
        p.t[0] = { emb_q, nullptr, q_nbr, emb_s, agg_W,         agg_b,       TA0,
                   agg_W + 2*16384, agg_b + 256, TA2,
                   kQN, iq, kD, kD, 0, kNQ, 0 };
        p.t[1] = { emb_s, nullptr, s_nbr, emb_q, agg_W + 16384, agg_b + 128, TA1,
                   nullptr, nullptr, nullptr,
                   kSN, is, kD, kD, 0, kNS, gq };
        p.t[2] = p.t[1];
        p.prep = { q_W, q_b, k_W, k_b, w_W, emb_r, W_ih, b_ih, b_hh, 1 };
        gemm_kernel<<<gq + gs + 1, 128, GEMM_SMEM>>>(p);
    }
    // level 1: TB0, TB1
    {
        GemmParams p;
        p.nt = 2;
        p.t[0] = { TA0, nullptr, q_nbr, TA1, agg_W,         agg_b,       TB0,
                   nullptr, nullptr, nullptr, kQN, iq, kD, kD, 0, kNQ, 0 };
        p.t[1] = { TA1, nullptr, s_nbr, TA2, agg_W + 16384, agg_b + 128, TB1,
                   nullptr, nullptr, nullptr, kSN, is, kD, kD, 0, kNS, gq };
        p.t[2] = p.t[1];
        p.prep = noprep;
        gemm_kernel<<<gq + gs, 128, GEMM_SMEM>>>(p);
    }
    // level2 + last + QTT fused
    chain3_kernel<<<gq, 128, GEMM_SMEM>>>(q_nbr, agg_W, agg_b, last_W, last_b, ft_W, ft_b);

    // gates: G[row] = QTT[question[row]] @ W_ih[:, {i,g,o}] (raw, RG added in combine)
    {
        GemmParams p;
        p.nt = 3;
        p.t[0] = { QTT, question, nullptr, nullptr, W_ih,       nullptr, G,
                   nullptr, nullptr, nullptr, 0, 0.f, 512, 384, 2, kB*kS, 0 };
        p.t[1] = { QTT, question, nullptr, nullptr, W_ih + 256, nullptr, G + 128,
                   nullptr, nullptr, nullptr, 0, 0.f, 512, 384, 2, kB*kS, gr };
        p.t[2] = { QTT, question, nullptr, nullptr, W_ih + 384, nullptr, G + 256,
                   nullptr, nullptr, nullptr, 0, 0.f, 512, 384, 2, kB*kS, 2*gr };
        p.prep = noprep;
        gemm_kernel<<<3*gr, 128, GEMM_SMEM>>>(p);
    }

    combine_kernel<<<(kB*kS)/16, 256>>>(response);

    dim3 pg(kT, kB);
    pred_kernel<<<pg, 32>>>(question, qs_sk, emb_q, emb_s, out);
}